// round 4
// baseline (speedup 1.0000x reference)
#include <cuda_runtime.h>
#include <math.h>

// Problem constants
#define HIDDEN   128
#define NPTS     1024
#define NPAIRS   (NPTS * NPTS)          // 1,048,576
#define G_TAB    8192                   // lookup-table rows over a in [0, 12]
#define PPB      16                     // pairs per block in the main kernel
#define PI_F     3.14159265358979323846f

// 4 MB lookup table: T[g][h] = f_h(a_g), a_g = g * 12/(G_TAB-1).  L2-resident.
static __device__ float g_table[G_TAB * HIDDEN];

// ---------------------------------------------------------------------------
// Kernel 1: build the table.  One block per grid row; 64 threads make the
// sinusoidal embedding into smem, then all 128 threads do the 128-long dot
// with their W row.  W (64 KB) stays hot in L1 across blocks.
// ---------------------------------------------------------------------------
__global__ __launch_bounds__(HIDDEN) void build_table_kernel(
    const float* __restrict__ W,   // [128][128] row-major
    const float* __restrict__ b)   // [128]
{
    __shared__ float emb[HIDDEN];
    const int g   = blockIdx.x;
    const int tid = threadIdx.x;

    const float a = (float)g * (12.0f / (float)(G_TAB - 1));

    if (tid < HIDDEN / 2) {
        // div_term[k] = exp(-k * ln(10000)/64), k = tid
        const float w     = expf(-(float)tid * (9.210340371976184f / 64.0f));
        const float omega = a * w;
        float s, c;
        sincosf(omega, &s, &c);
        emb[2 * tid]     = s;
        emb[2 * tid + 1] = c;
    }
    __syncthreads();

    float acc = b[tid];
    const float* wr = W + tid * HIDDEN;
#pragma unroll 16
    for (int d = 0; d < HIDDEN; ++d)
        acc = fmaf(emb[d], wr[d], acc);

    g_table[g * HIDDEN + tid] = acc;
}

// ---------------------------------------------------------------------------
// Kernel 2: main.  Each block handles PPB=16 pairs.
//   Phase 1: 16 threads compute (g, frac) for their pair (1 atan2 per pair).
//   Phase 2: each of the 4 warps lerps one pair's 128-float row per
//            iteration (float4 per lane): 2 x 512B L2 loads + 512B store.
// ---------------------------------------------------------------------------
__global__ __launch_bounds__(HIDDEN) void geom_embed_kernel(
    const float* __restrict__ normals,  // [1024][3]
    float*       __restrict__ out)      // [1024*1024][128]
{
    __shared__ int   s_g[PPB];
    __shared__ float s_f[PPB];

    const int  tid   = threadIdx.x;
    const long pbase = (long)blockIdx.x * PPB;

    if (tid < PPB) {
        const int p = (int)pbase + tid;
        const int i = p >> 10;
        const int j = p & (NPTS - 1);

        const float ax = normals[i * 3 + 0];
        const float ay = normals[i * 3 + 1];
        const float az = normals[i * 3 + 2];
        const float bx = normals[j * 3 + 0];
        const float by = normals[j * 3 + 1];
        const float bz = normals[j * 3 + 2];

        const float cx = ay * bz - az * by;
        const float cy = az * bx - ax * bz;
        const float cz = ax * by - ay * bx;

        const float sv  = sqrtf(cx * cx + cy * cy + cz * cz);
        const float cv  = ax * bx + ay * by + az * bz;
        const float ang = atan2f(sv, cv);            // in [0, pi]

        // u = a * (G-1)/12 = ang * (G-1)/pi
        float u = ang * ((float)(G_TAB - 1) / PI_F);
        u = fminf(fmaxf(u, 0.0f), (float)(G_TAB - 1));
        int gi = (int)u;
        if (gi > G_TAB - 2) gi = G_TAB - 2;
        s_g[tid] = gi;
        s_f[tid] = u - (float)gi;
    }
    __syncthreads();

    const int warp = tid >> 5;
    const int lane = tid & 31;

    const float4* __restrict__ T4 = (const float4*)g_table;   // 32 float4 per row
    float4* __restrict__ out4     = (float4*)out;

#pragma unroll
    for (int it = 0; it < PPB / 4; ++it) {
        const int   pl = warp + it * 4;       // pair-local index handled by this warp
        const int   gi = s_g[pl];
        const float f  = s_f[pl];

        const float4 c0 = T4[gi * 32 + lane];
        const float4 c1 = T4[gi * 32 + 32 + lane];

        float4 r;
        r.x = fmaf(f, c1.x - c0.x, c0.x);
        r.y = fmaf(f, c1.y - c0.y, c0.y);
        r.z = fmaf(f, c1.z - c0.z, c0.z);
        r.w = fmaf(f, c1.w - c0.w, c0.w);

        out4[(pbase + pl) * 32 + lane] = r;
    }
}

// ---------------------------------------------------------------------------
// Launch.  Inputs (metadata order): points[unused], normals, W, b.
// ---------------------------------------------------------------------------
extern "C" void kernel_launch(void* const* d_in, const int* in_sizes, int n_in,
                              void* d_out, int out_size)
{
    const float* normals = (const float*)d_in[1];
    const float* W       = (const float*)d_in[2];
    const float* b       = (const float*)d_in[3];
    float* out           = (float*)d_out;

    build_table_kernel<<<G_TAB, HIDDEN>>>(W, b);
    geom_embed_kernel<<<NPAIRS / PPB, HIDDEN>>>(normals, out);
}

// round 6
// speedup vs baseline: 9.0744x; 9.0744x over previous
#include <cuda_runtime.h>
#include <math.h>

// Problem constants
#define HIDDEN   128
#define NPTS     1024
#define NPAIRS   (NPTS * NPTS)          // 1,048,576
#define G_TAB    2048                   // lookup-table rows over a in [0, 12]
#define PPB      16                     // pairs per block in the main kernel
#define PI_F     3.14159265358979323846f

// 1 MB lookup table: T[g][h] = f_h(a_g), a_g = g * 12/(G_TAB-1).  L2-resident.
static __device__ float g_table[G_TAB * HIDDEN];
// Transposed weights: Wt[d][h] = W[h][d]  (for coalesced reads in build kernel)
static __device__ float g_Wt[HIDDEN * HIDDEN];

// ---------------------------------------------------------------------------
// Kernel 0: transpose W (tiny; uncoalesced reads but only 16K elements).
// ---------------------------------------------------------------------------
__global__ __launch_bounds__(HIDDEN) void transpose_W_kernel(
    const float* __restrict__ W)
{
    const int d = blockIdx.x;     // 0..127
    const int h = threadIdx.x;    // 0..127
    g_Wt[d * HIDDEN + h] = W[h * HIDDEN + d];
}

// ---------------------------------------------------------------------------
// Kernel 1: build the table.  One block per grid row; 64 threads make the
// sinusoidal embedding into smem, then all 128 threads do the 128-long dot.
// Wt is read coalesced (one 128B line per warp per iteration, L1-hot).
// ---------------------------------------------------------------------------
__global__ __launch_bounds__(HIDDEN) void build_table_kernel(
    const float* __restrict__ b)   // [128]
{
    __shared__ float emb[HIDDEN];
    const int g   = blockIdx.x;
    const int tid = threadIdx.x;

    const float a = (float)g * (12.0f / (float)(G_TAB - 1));

    if (tid < HIDDEN / 2) {
        // div_term[k] = exp(-k * ln(10000)/64), k = tid
        const float w     = expf(-(float)tid * (9.210340371976184f / 64.0f));
        const float omega = a * w;
        float s, c;
        sincosf(omega, &s, &c);
        emb[2 * tid]     = s;
        emb[2 * tid + 1] = c;
    }
    __syncthreads();

    float acc = b[tid];
#pragma unroll 16
    for (int d = 0; d < HIDDEN; ++d)
        acc = fmaf(emb[d], g_Wt[d * HIDDEN + tid], acc);

    g_table[g * HIDDEN + tid] = acc;
}

// ---------------------------------------------------------------------------
// Kernel 2: main.  Each block handles PPB=16 pairs.
//   Phase 1: 16 threads compute (g, frac) for their pair (1 atan2 per pair).
//   Phase 2: each of the 4 warps lerps one pair's 128-float row per
//            iteration (float4 per lane): 2 x 512B L2 loads + 512B store.
// ---------------------------------------------------------------------------
__global__ __launch_bounds__(HIDDEN) void geom_embed_kernel(
    const float* __restrict__ normals,  // [1024][3]
    float*       __restrict__ out)      // [1024*1024][128]
{
    __shared__ int   s_g[PPB];
    __shared__ float s_f[PPB];

    const int  tid   = threadIdx.x;
    const long pbase = (long)blockIdx.x * PPB;

    if (tid < PPB) {
        const int p = (int)pbase + tid;
        const int i = p >> 10;
        const int j = p & (NPTS - 1);

        const float ax = normals[i * 3 + 0];
        const float ay = normals[i * 3 + 1];
        const float az = normals[i * 3 + 2];
        const float bx = normals[j * 3 + 0];
        const float by = normals[j * 3 + 1];
        const float bz = normals[j * 3 + 2];

        const float cx = ay * bz - az * by;
        const float cy = az * bx - ax * bz;
        const float cz = ax * by - ay * bx;

        const float sv  = sqrtf(cx * cx + cy * cy + cz * cz);
        const float cv  = ax * bx + ay * by + az * bz;
        const float ang = atan2f(sv, cv);            // in [0, pi]

        // u = a * (G-1)/12 = ang * (G-1)/pi
        float u = ang * ((float)(G_TAB - 1) / PI_F);
        u = fminf(fmaxf(u, 0.0f), (float)(G_TAB - 1));
        int gi = (int)u;
        if (gi > G_TAB - 2) gi = G_TAB - 2;
        s_g[tid] = gi;
        s_f[tid] = u - (float)gi;
    }
    __syncthreads();

    const int warp = tid >> 5;
    const int lane = tid & 31;

    const float4* __restrict__ T4 = (const float4*)g_table;   // 32 float4 per row
    float4* __restrict__ out4     = (float4*)out;

#pragma unroll
    for (int it = 0; it < PPB / 4; ++it) {
        const int   pl = warp + it * 4;       // pair-local index handled by this warp
        const int   gi = s_g[pl];
        const float f  = s_f[pl];

        const float4 c0 = T4[gi * 32 + lane];
        const float4 c1 = T4[gi * 32 + 32 + lane];

        float4 r;
        r.x = fmaf(f, c1.x - c0.x, c0.x);
        r.y = fmaf(f, c1.y - c0.y, c0.y);
        r.z = fmaf(f, c1.z - c0.z, c0.z);
        r.w = fmaf(f, c1.w - c0.w, c0.w);

        out4[(pbase + pl) * 32 + lane] = r;
    }
}

// ---------------------------------------------------------------------------
// Launch.  Inputs (metadata order): points[unused], normals, W, b.
// ---------------------------------------------------------------------------
extern "C" void kernel_launch(void* const* d_in, const int* in_sizes, int n_in,
                              void* d_out, int out_size)
{
    const float* normals = (const float*)d_in[1];
    const float* W       = (const float*)d_in[2];
    const float* b       = (const float*)d_in[3];
    float* out           = (float*)d_out;

    transpose_W_kernel<<<HIDDEN, HIDDEN>>>(W);
    build_table_kernel<<<G_TAB, HIDDEN>>>(b);
    geom_embed_kernel<<<NPAIRS / PPB, HIDDEN>>>(normals, out);
}

// round 7
// speedup vs baseline: 10.4360x; 1.1501x over previous
#include <cuda_runtime.h>
#include <math.h>

// Problem constants
#define HIDDEN   128
#define NPTS     1024
#define NPAIRS   (NPTS * NPTS)          // 1,048,576
#define G_TAB    512                    // lookup-table rows over a in [0, 12]
#define PPB      16                     // pairs per block in the main kernel
#define PI_F     3.14159265358979323846f

// 256 KB lookup table: T[g][h] = f_h(a_g), a_g = g * 12/(G_TAB-1).
// Small enough to be (nearly) L1-resident in the main kernel.
static __device__ float g_table[G_TAB * HIDDEN];
// Transposed weights: Wt[d][h] = W[h][d]  (for coalesced reads in build kernel)
static __device__ float g_Wt[HIDDEN * HIDDEN];

// ---------------------------------------------------------------------------
// Kernel 0: transpose W (tiny; uncoalesced reads but only 16K elements).
// ---------------------------------------------------------------------------
__global__ __launch_bounds__(HIDDEN) void transpose_W_kernel(
    const float* __restrict__ W)
{
    const int d = blockIdx.x;     // 0..127
    const int h = threadIdx.x;    // 0..127
    g_Wt[d * HIDDEN + h] = W[h * HIDDEN + d];
}

// ---------------------------------------------------------------------------
// Kernel 1: build the table.  One block per grid row; 64 threads make the
// sinusoidal embedding into smem, then all 128 threads do the 128-long dot.
// Wt is read coalesced (one 128B line per warp per iteration, L1-hot).
// ---------------------------------------------------------------------------
__global__ __launch_bounds__(HIDDEN) void build_table_kernel(
    const float* __restrict__ b)   // [128]
{
    __shared__ float emb[HIDDEN];
    const int g   = blockIdx.x;
    const int tid = threadIdx.x;

    const float a = (float)g * (12.0f / (float)(G_TAB - 1));

    if (tid < HIDDEN / 2) {
        // div_term[k] = exp(-k * ln(10000)/64), k = tid
        const float w     = expf(-(float)tid * (9.210340371976184f / 64.0f));
        const float omega = a * w;
        float s, c;
        sincosf(omega, &s, &c);
        emb[2 * tid]     = s;
        emb[2 * tid + 1] = c;
    }
    __syncthreads();

    float acc = b[tid];
#pragma unroll 16
    for (int d = 0; d < HIDDEN; ++d)
        acc = fmaf(emb[d], g_Wt[d * HIDDEN + tid], acc);

    g_table[g * HIDDEN + tid] = acc;
}

// ---------------------------------------------------------------------------
// Kernel 2: main.  Each block handles PPB=16 pairs.
//   Phase 1: 16 threads compute (g, frac) for their pair (1 atan2 per pair).
//   Phase 2: each of the 4 warps lerps one pair's 128-float row per
//            iteration (float4 per lane): 2 x 512B table loads (L1-hot)
//            + 512B coalesced store.
// ---------------------------------------------------------------------------
__global__ __launch_bounds__(HIDDEN) void geom_embed_kernel(
    const float* __restrict__ normals,  // [1024][3]
    float*       __restrict__ out)      // [1024*1024][128]
{
    __shared__ int   s_g[PPB];
    __shared__ float s_f[PPB];

    const int  tid   = threadIdx.x;
    const long pbase = (long)blockIdx.x * PPB;

    if (tid < PPB) {
        const int p = (int)pbase + tid;
        const int i = p >> 10;
        const int j = p & (NPTS - 1);

        const float ax = normals[i * 3 + 0];
        const float ay = normals[i * 3 + 1];
        const float az = normals[i * 3 + 2];
        const float bx = normals[j * 3 + 0];
        const float by = normals[j * 3 + 1];
        const float bz = normals[j * 3 + 2];

        const float cx = ay * bz - az * by;
        const float cy = az * bx - ax * bz;
        const float cz = ax * by - ay * bx;

        const float sv  = sqrtf(cx * cx + cy * cy + cz * cz);
        const float cv  = ax * bx + ay * by + az * bz;
        const float ang = atan2f(sv, cv);            // in [0, pi]

        // u = a * (G-1)/12 = ang * (G-1)/pi
        float u = ang * ((float)(G_TAB - 1) / PI_F);
        u = fminf(fmaxf(u, 0.0f), (float)(G_TAB - 1));
        int gi = (int)u;
        if (gi > G_TAB - 2) gi = G_TAB - 2;
        s_g[tid] = gi;
        s_f[tid] = u - (float)gi;
    }
    __syncthreads();

    const int warp = tid >> 5;
    const int lane = tid & 31;

    const float4* __restrict__ T4 = (const float4*)g_table;   // 32 float4 per row
    float4* __restrict__ out4     = (float4*)out;

#pragma unroll
    for (int it = 0; it < PPB / 4; ++it) {
        const int   pl = warp + it * 4;       // pair-local index handled by this warp
        const int   gi = s_g[pl];
        const float f  = s_f[pl];

        const float4 c0 = T4[gi * 32 + lane];
        const float4 c1 = T4[gi * 32 + 32 + lane];

        float4 r;
        r.x = fmaf(f, c1.x - c0.x, c0.x);
        r.y = fmaf(f, c1.y - c0.y, c0.y);
        r.z = fmaf(f, c1.z - c0.z, c0.z);
        r.w = fmaf(f, c1.w - c0.w, c0.w);

        out4[(pbase + pl) * 32 + lane] = r;
    }
}

// ---------------------------------------------------------------------------
// Launch.  Inputs (metadata order): points[unused], normals, W, b.
// ---------------------------------------------------------------------------
extern "C" void kernel_launch(void* const* d_in, const int* in_sizes, int n_in,
                              void* d_out, int out_size)
{
    const float* normals = (const float*)d_in[1];
    const float* W       = (const float*)d_in[2];
    const float* b       = (const float*)d_in[3];
    float* out           = (float*)d_out;

    transpose_W_kernel<<<HIDDEN, HIDDEN>>>(W);
    build_table_kernel<<<G_TAB, HIDDEN>>>(b);
    geom_embed_kernel<<<NPAIRS / PPB, HIDDEN>>>(normals, out);
}

// round 8
// speedup vs baseline: 10.9416x; 1.0484x over previous
#include <cuda_runtime.h>
#include <math.h>

// Problem constants
#define HIDDEN   128
#define NPTS     1024
#define NPAIRS   (NPTS * NPTS)          // 1,048,576
#define G_TAB    512                    // lookup-table rows over a in [0, 12]
#define PPB      16                     // pairs per block in the main kernel
#define PI_F     3.14159265358979323846f

// 256 KB lookup table: T[g][h] = f_h(a_g), a_g = g * 12/(G_TAB-1).
// Small enough to be (nearly) L1-resident in the main kernel.
static __device__ float g_table[G_TAB * HIDDEN];

// ---------------------------------------------------------------------------
// Kernel 1: build the table (fused, no transpose needed).
// One block per grid row g.  64 threads build the sinusoidal embedding into
// smem; then each warp computes 32 output channels via warp-cooperative dot:
// lane l loads W[c][4l..4l+3] (coalesced 128B row segment, L1-hot), FMAs with
// emb[4l..4l+3], and a butterfly reduction produces the channel value.
// ---------------------------------------------------------------------------
__global__ __launch_bounds__(HIDDEN) void build_table_kernel(
    const float* __restrict__ W,   // [128][128] row-major
    const float* __restrict__ b)   // [128]
{
    __shared__ float emb[HIDDEN];
    const int g    = blockIdx.x;
    const int tid  = threadIdx.x;
    const int warp = tid >> 5;
    const int lane = tid & 31;

    const float a = (float)g * (12.0f / (float)(G_TAB - 1));

    if (tid < HIDDEN / 2) {
        // div_term[k] = exp(-k * ln(10000)/64), k = tid
        const float w     = expf(-(float)tid * (9.210340371976184f / 64.0f));
        const float omega = a * w;
        float s, c;
        sincosf(omega, &s, &c);
        emb[2 * tid]     = s;
        emb[2 * tid + 1] = c;
    }
    __syncthreads();

    // Lane-private embedding chunk (smem LDS.128, conflict-free)
    const float4 e = ((const float4*)emb)[lane];

    const float4* __restrict__ W4 = (const float4*)W;   // 32 float4 per row

#pragma unroll
    for (int k = 0; k < 32; ++k) {
        const int c = warp * 32 + k;                    // channel this warp computes
        const float4 wv = W4[c * 32 + lane];

        float s = e.x * wv.x;
        s = fmaf(e.y, wv.y, s);
        s = fmaf(e.z, wv.z, s);
        s = fmaf(e.w, wv.w, s);

        // Butterfly reduction across the warp
#pragma unroll
        for (int off = 16; off > 0; off >>= 1)
            s += __shfl_xor_sync(0xFFFFFFFFu, s, off);

        if (lane == 0)
            g_table[g * HIDDEN + c] = s + b[c];
    }
}

// ---------------------------------------------------------------------------
// Kernel 2: main.  Each block handles PPB=16 pairs.
//   Phase 1: 16 threads compute (g, frac) for their pair (1 atan2 per pair).
//   Phase 2: each of the 4 warps lerps one pair's 128-float row per
//            iteration (float4 per lane): 2 x 512B table loads (L1-hot)
//            + 512B coalesced streaming store.
// ---------------------------------------------------------------------------
__global__ __launch_bounds__(HIDDEN) void geom_embed_kernel(
    const float* __restrict__ normals,  // [1024][3]
    float*       __restrict__ out)      // [1024*1024][128]
{
    __shared__ int   s_g[PPB];
    __shared__ float s_f[PPB];

    const int  tid   = threadIdx.x;
    const long pbase = (long)blockIdx.x * PPB;

    if (tid < PPB) {
        const int p = (int)pbase + tid;
        const int i = p >> 10;
        const int j = p & (NPTS - 1);

        const float ax = normals[i * 3 + 0];
        const float ay = normals[i * 3 + 1];
        const float az = normals[i * 3 + 2];
        const float bx = normals[j * 3 + 0];
        const float by = normals[j * 3 + 1];
        const float bz = normals[j * 3 + 2];

        const float cx = ay * bz - az * by;
        const float cy = az * bx - ax * bz;
        const float cz = ax * by - ay * bx;

        const float sv  = sqrtf(cx * cx + cy * cy + cz * cz);
        const float cv  = ax * bx + ay * by + az * bz;
        const float ang = atan2f(sv, cv);            // in [0, pi]

        // u = a * (G-1)/12 = ang * (G-1)/pi
        float u = ang * ((float)(G_TAB - 1) / PI_F);
        u = fminf(fmaxf(u, 0.0f), (float)(G_TAB - 1));
        int gi = (int)u;
        if (gi > G_TAB - 2) gi = G_TAB - 2;
        s_g[tid] = gi;
        s_f[tid] = u - (float)gi;
    }
    __syncthreads();

    const int warp = tid >> 5;
    const int lane = tid & 31;

    const float4* __restrict__ T4 = (const float4*)g_table;   // 32 float4 per row
    float4* __restrict__ out4     = (float4*)out;

#pragma unroll
    for (int it = 0; it < PPB / 4; ++it) {
        const int   pl = warp + it * 4;       // pair-local index handled by this warp
        const int   gi = s_g[pl];
        const float f  = s_f[pl];

        const float4 c0 = T4[gi * 32 + lane];
        const float4 c1 = T4[gi * 32 + 32 + lane];

        float4 r;
        r.x = fmaf(f, c1.x - c0.x, c0.x);
        r.y = fmaf(f, c1.y - c0.y, c0.y);
        r.z = fmaf(f, c1.z - c0.z, c0.z);
        r.w = fmaf(f, c1.w - c0.w, c0.w);

        // Streaming store: output is never re-read, keep table lines resident.
        __stcs(&out4[(pbase + pl) * 32 + lane], r);
    }
}

// ---------------------------------------------------------------------------
// Launch.  Inputs (metadata order): points[unused], normals, W, b.
// ---------------------------------------------------------------------------
extern "C" void kernel_launch(void* const* d_in, const int* in_sizes, int n_in,
                              void* d_out, int out_size)
{
    const float* normals = (const float*)d_in[1];
    const float* W       = (const float*)d_in[2];
    const float* b       = (const float*)d_in[3];
    float* out           = (float*)d_out;

    build_table_kernel<<<G_TAB, HIDDEN>>>(W, b);
    geom_embed_kernel<<<NPAIRS / PPB, HIDDEN>>>(normals, out);
}

// round 9
// speedup vs baseline: 11.1287x; 1.0171x over previous
#include <cuda_runtime.h>
#include <math.h>

// Problem constants
#define HIDDEN   128
#define NPTS     1024
#define NPAIRS   (NPTS * NPTS)          // 1,048,576
#define G_TAB    128                    // lookup-table rows over a in [0, 12]
#define PPB      16                     // pairs per block in the main kernel
#define PI_F     3.14159265358979323846f

// 64 KB lookup table: T[g][h] = f_h(a_g), a_g = g * 12/(G_TAB-1).
// Fully L1-resident in the main kernel.
static __device__ float g_table[G_TAB * HIDDEN];

// ---------------------------------------------------------------------------
// Kernel 1: build the table (fused, no transpose needed).
// One block per grid row g.  64 threads build the sinusoidal embedding into
// smem; then each warp computes 32 output channels via warp-cooperative dot:
// lane l loads W[c][4l..4l+3] (coalesced 128B row segment, L1-hot), FMAs with
// emb[4l..4l+3], and a butterfly reduction produces the channel value.
// ---------------------------------------------------------------------------
__global__ __launch_bounds__(HIDDEN) void build_table_kernel(
    const float* __restrict__ W,   // [128][128] row-major
    const float* __restrict__ b)   // [128]
{
    __shared__ float emb[HIDDEN];
    const int g    = blockIdx.x;
    const int tid  = threadIdx.x;
    const int warp = tid >> 5;
    const int lane = tid & 31;

    const float a = (float)g * (12.0f / (float)(G_TAB - 1));

    if (tid < HIDDEN / 2) {
        // div_term[k] = exp(-k * ln(10000)/64), k = tid
        const float w     = expf(-(float)tid * (9.210340371976184f / 64.0f));
        const float omega = a * w;
        float s, c;
        sincosf(omega, &s, &c);
        emb[2 * tid]     = s;
        emb[2 * tid + 1] = c;
    }
    __syncthreads();

    // Lane-private embedding chunk (smem LDS.128, conflict-free)
    const float4 e = ((const float4*)emb)[lane];

    const float4* __restrict__ W4 = (const float4*)W;   // 32 float4 per row

#pragma unroll
    for (int k = 0; k < 32; ++k) {
        const int c = warp * 32 + k;                    // channel this warp computes
        const float4 wv = W4[c * 32 + lane];

        float s = e.x * wv.x;
        s = fmaf(e.y, wv.y, s);
        s = fmaf(e.z, wv.z, s);
        s = fmaf(e.w, wv.w, s);

        // Butterfly reduction across the warp
#pragma unroll
        for (int off = 16; off > 0; off >>= 1)
            s += __shfl_xor_sync(0xFFFFFFFFu, s, off);

        if (lane == 0)
            g_table[g * HIDDEN + c] = s + b[c];
    }
}

// ---------------------------------------------------------------------------
// Kernel 2: main.  Each block handles PPB=16 pairs.
//   Phase 1: 16 threads compute (g, frac) for their pair (1 atan2 per pair).
//   Phase 2: each of the 4 warps lerps one pair's 128-float row per
//            iteration (float4 per lane): 2 x 512B table loads (L1-hot)
//            + 512B coalesced streaming store.
// ---------------------------------------------------------------------------
__global__ __launch_bounds__(HIDDEN) void geom_embed_kernel(
    const float* __restrict__ normals,  // [1024][3]
    float*       __restrict__ out)      // [1024*1024][128]
{
    __shared__ int   s_g[PPB];
    __shared__ float s_f[PPB];

    const int  tid   = threadIdx.x;
    const long pbase = (long)blockIdx.x * PPB;

    if (tid < PPB) {
        const int p = (int)pbase + tid;
        const int i = p >> 10;
        const int j = p & (NPTS - 1);

        const float ax = normals[i * 3 + 0];
        const float ay = normals[i * 3 + 1];
        const float az = normals[i * 3 + 2];
        const float bx = normals[j * 3 + 0];
        const float by = normals[j * 3 + 1];
        const float bz = normals[j * 3 + 2];

        const float cx = ay * bz - az * by;
        const float cy = az * bx - ax * bz;
        const float cz = ax * by - ay * bx;

        const float sv  = sqrtf(cx * cx + cy * cy + cz * cz);
        const float cv  = ax * bx + ay * by + az * bz;
        const float ang = atan2f(sv, cv);            // in [0, pi]

        // u = a * (G-1)/12 = ang * (G-1)/pi
        float u = ang * ((float)(G_TAB - 1) / PI_F);
        u = fminf(fmaxf(u, 0.0f), (float)(G_TAB - 1));
        int gi = (int)u;
        if (gi > G_TAB - 2) gi = G_TAB - 2;
        s_g[tid] = gi;
        s_f[tid] = u - (float)gi;
    }
    __syncthreads();

    const int warp = tid >> 5;
    const int lane = tid & 31;

    const float4* __restrict__ T4 = (const float4*)g_table;   // 32 float4 per row
    float4* __restrict__ out4     = (float4*)out;

#pragma unroll
    for (int it = 0; it < PPB / 4; ++it) {
        const int   pl = warp + it * 4;       // pair-local index handled by this warp
        const int   gi = s_g[pl];
        const float f  = s_f[pl];

        const float4 c0 = T4[gi * 32 + lane];
        const float4 c1 = T4[gi * 32 + 32 + lane];

        float4 r;
        r.x = fmaf(f, c1.x - c0.x, c0.x);
        r.y = fmaf(f, c1.y - c0.y, c0.y);
        r.z = fmaf(f, c1.z - c0.z, c0.z);
        r.w = fmaf(f, c1.w - c0.w, c0.w);

        // Streaming store: output is never re-read, keep table lines resident.
        __stcs(&out4[(pbase + pl) * 32 + lane], r);
    }
}

// ---------------------------------------------------------------------------
// Launch.  Inputs (metadata order): points[unused], normals, W, b.
// ---------------------------------------------------------------------------
extern "C" void kernel_launch(void* const* d_in, const int* in_sizes, int n_in,
                              void* d_out, int out_size)
{
    const float* normals = (const float*)d_in[1];
    const float* W       = (const float*)d_in[2];
    const float* b       = (const float*)d_in[3];
    float* out           = (float*)d_out;

    build_table_kernel<<<G_TAB, HIDDEN>>>(W, b);
    geom_embed_kernel<<<NPAIRS / PPB, HIDDEN>>>(normals, out);
}